// round 6
// baseline (speedup 1.0000x reference)
#include <cuda_runtime.h>
#include <cuda.h>
#include <cstdint>

#define N_BATCH 65536
#define T_STEPS 512
#define BN 128                     // threads per block (4 warps)
#define BT 32                      // timesteps per chunk (128B rows -> SW128)
#define NCHUNK (T_STEPS / BT)      // 16
#define WTILE_BYTES (32 * BT * 4)  // 4096: one warp's 32 rows x 128B
#define NBUF 3
#define NWARPS (BN / 32)
#define SMEM_TOTAL (1024 + NWARPS * NBUF * WTILE_BYTES)   // 1024 + 48KB

// ---------------- PTX helpers ----------------
__device__ __forceinline__ uint32_t smem_u32(const void* p) {
    return (uint32_t)__cvta_generic_to_shared(p);
}
__device__ __forceinline__ void mbar_init(uint32_t mbar, uint32_t cnt) {
    asm volatile("mbarrier.init.shared.b64 [%0], %1;" :: "r"(mbar), "r"(cnt) : "memory");
}
__device__ __forceinline__ void mbar_expect_tx(uint32_t mbar, uint32_t bytes) {
    asm volatile("mbarrier.arrive.expect_tx.shared.b64 _, [%0], %1;"
                 :: "r"(mbar), "r"(bytes) : "memory");
}
__device__ __forceinline__ void mbar_wait(uint32_t mbar, uint32_t parity) {
    asm volatile(
        "{\n\t.reg .pred P;\n"
        "WAITLOOP_%=:\n\t"
        "mbarrier.try_wait.parity.acquire.cta.shared::cta.b64 P, [%0], %1, 0x989680;\n\t"
        "@P bra.uni WAITDONE_%=;\n\t"
        "bra.uni WAITLOOP_%=;\n"
        "WAITDONE_%=:\n\t}"
        :: "r"(mbar), "r"(parity) : "memory");
}
__device__ __forceinline__ void tma_load2d(uint32_t smem_dst, const CUtensorMap* map,
                                           int cx, int cy, uint32_t mbar) {
    asm volatile("cp.async.bulk.tensor.2d.shared::cta.global.tile.mbarrier::complete_tx::bytes"
                 " [%0], [%1, {%2, %3}], [%4];"
                 :: "r"(smem_dst), "l"(map), "r"(cx), "r"(cy), "r"(mbar) : "memory");
}
__device__ __forceinline__ void tma_store2d(const CUtensorMap* map, int cx, int cy,
                                            uint32_t smem_src) {
    asm volatile("cp.async.bulk.tensor.2d.global.shared::cta.tile.bulk_group"
                 " [%0, {%1, %2}], [%3];"
                 :: "l"(map), "r"(cx), "r"(cy), "r"(smem_src) : "memory");
}
__device__ __forceinline__ void tma_commit() {
    asm volatile("cp.async.bulk.commit_group;" ::: "memory");
}
__device__ __forceinline__ void tma_wait_read1() {
    asm volatile("cp.async.bulk.wait_group.read 1;" ::: "memory");
}
__device__ __forceinline__ void tma_wait_all() {
    asm volatile("cp.async.bulk.wait_group 0;" ::: "memory");
}
__device__ __forceinline__ void fence_proxy_async_cta() {
    asm volatile("fence.proxy.async.shared::cta;" ::: "memory");
}

// SW128 swizzle for 128B rows: 16B unit u at row r lives at r*128 + (u ^ (r&7))*16
__device__ __forceinline__ uint32_t sw_off(int row, int u) {
    return (uint32_t)(row * 128 + ((u ^ (row & 7)) << 4));
}

// ---------------- warp-autonomous TMA kernel ----------------
__global__ __launch_bounds__(BN) void lif_tma_kernel(
    const __grid_constant__ CUtensorMap x_map,
    const __grid_constant__ CUtensorMap mem_map,
    const float* __restrict__ beta_p,
    const float* __restrict__ thr_p,
    const float* __restrict__ init_u,
    float* __restrict__ out)
{
    extern __shared__ char smem[];
    uint32_t mbar_base = smem_u32(smem);        // NWARPS*NBUF mbarriers, 8B each
    char* tiles = smem + 1024;                  // 1024-aligned tiles

    const int tid  = threadIdx.x;
    const int lane = tid & 31;
    const int w    = tid >> 5;
    const int n0   = blockIdx.x * BN;
    const int nw0  = n0 + w * 32;               // this warp's first neuron row

    const float beta = 1.0f / (1.0f + __expf(-beta_p[0]));
    const float thr  = thr_p[0];
    float mem = init_u[nw0 + lane] * thr;

    float* spikes = out;

    char* wtiles = tiles + w * NBUF * WTILE_BYTES;
    const uint32_t wmbar = mbar_base + (uint32_t)(w * NBUF) * 8u;

    // init all mbarriers (one thread), single block barrier, then warps diverge
    if (tid < NWARPS * NBUF) mbar_init(mbar_base + tid * 8u, 1);
    __syncthreads();

    if (lane == 0) {
        fence_proxy_async_cta();
        mbar_expect_tx(wmbar + 0, WTILE_BYTES);
        tma_load2d(smem_u32(wtiles + 0 * WTILE_BYTES), &x_map, 0, nw0, wmbar + 0);
        mbar_expect_tx(wmbar + 8, WTILE_BYTES);
        tma_load2d(smem_u32(wtiles + 1 * WTILE_BYTES), &x_map, BT, nw0, wmbar + 8);
    }

    const int g8  = lane & 7;                   // ballot group this lane keeps
    const int sub = lane >> 3;                  // 0..3

    #pragma unroll 1
    for (int c = 0; c < NCHUNK; ++c) {
        const int buf = c % NBUF;
        char* tile = wtiles + buf * WTILE_BYTES;

        mbar_wait(wmbar + 8u * buf, (uint32_t)((c / NBUF) & 1));

        // ---- scan: read x (SW128), write mem_in in place, collect ballots ----
        uint32_t k0 = 0, k1 = 0, k2 = 0, k3 = 0;
        #pragma unroll
        for (int t4 = 0; t4 < 8; ++t4) {
            float4* slot = (float4*)(tile + sw_off(lane, t4));
            float4 xv = *slot;
            float4 mv;
            uint32_t b0, b1, b2, b3;

            mv.x = mem;
            float mu = fmaf(beta, mem, xv.x);
            float s  = mu - thr;
            bool  p  = (s >= 0.0f);
            b0 = __ballot_sync(0xffffffffu, p);
            mem = p ? s : mu;

            mv.y = mem;
            mu = fmaf(beta, mem, xv.y);
            s  = mu - thr;
            p  = (s >= 0.0f);
            b1 = __ballot_sync(0xffffffffu, p);
            mem = p ? s : mu;

            mv.z = mem;
            mu = fmaf(beta, mem, xv.z);
            s  = mu - thr;
            p  = (s >= 0.0f);
            b2 = __ballot_sync(0xffffffffu, p);
            mem = p ? s : mu;

            mv.w = mem;
            mu = fmaf(beta, mem, xv.w);
            s  = mu - thr;
            p  = (s >= 0.0f);
            b3 = __ballot_sync(0xffffffffu, p);
            mem = p ? s : mu;

            *slot = mv;                          // mem_in tile, in place (SW128)

            if (g8 == t4) { k0 = b0; k1 = b1; k2 = b2; k3 = b3; }
        }
        __syncwarp();                            // warp's 32 rows all written

        // ---- lane 0: TMA store mem tile; prefetch chunk c+2 (warp-local) ----
        if (lane == 0) {
            fence_proxy_async_cta();
            tma_store2d(&mem_map, c * BT, nw0, smem_u32(tile));
            tma_commit();
            if (c + 2 < NCHUNK) {
                tma_wait_read1();                // store c-1 read-done -> buffer free
                const int nbuf = (c + 2) % NBUF;
                mbar_expect_tx(wmbar + 8u * nbuf, WTILE_BYTES);
                tma_load2d(smem_u32(wtiles + nbuf * WTILE_BYTES), &x_map,
                           (c + 2) * BT, nw0, wmbar + 8u * nbuf);
            }
        }

        // ---- spikes: bit-extract from ballots, coalesced STG.128 ----
        {
            const int tbase = c * BT + g8 * 4;
            #pragma unroll
            for (int pp = 0; pp < 8; ++pp) {
                const int bit = pp * 4 + sub;
                const int n   = nw0 + pp * 4 + sub;
                float4 sv;
                sv.x = ((k0 >> bit) & 1u) ? 1.0f : 0.0f;
                sv.y = ((k1 >> bit) & 1u) ? 1.0f : 0.0f;
                sv.z = ((k2 >> bit) & 1u) ? 1.0f : 0.0f;
                sv.w = ((k3 >> bit) & 1u) ? 1.0f : 0.0f;
                *(float4*)(spikes + (size_t)n * T_STEPS + tbase) = sv;
            }
        }
    }

    if (lane == 0) tma_wait_all();               // drain this warp's mem stores
}

// ---------------- fallback (Round-3 kernel, proven) ----------------
#define PAD 36
#define TILE_W (BN * PAD)
#define FB_SMEM (3 * TILE_W * 4)

__device__ __forceinline__ void cp_async16(uint32_t smem_addr, const void* gptr) {
    asm volatile("cp.async.cg.shared.global [%0], [%1], 16;\n"
                 :: "r"(smem_addr), "l"(gptr) : "memory");
}
__device__ __forceinline__ void cp_commit() {
    asm volatile("cp.async.commit_group;\n" ::: "memory");
}
__device__ __forceinline__ void cp_wait0() {
    asm volatile("cp.async.wait_group 0;\n" ::: "memory");
}

__global__ __launch_bounds__(BN) void lif_fallback(
    const float* __restrict__ x, const float* __restrict__ beta_p,
    const float* __restrict__ thr_p, const float* __restrict__ init_u,
    float* __restrict__ out)
{
    extern __shared__ float smemf[];
    float* bufA = smemf;
    float* bufB = smemf + TILE_W;
    float* sspk = smemf + 2 * TILE_W;

    const int tid = threadIdx.x;
    const int n0  = blockIdx.x * BN;
    const float beta = 1.0f / (1.0f + __expf(-beta_p[0]));
    const float thr  = thr_p[0];
    float mem = init_u[n0 + tid] * thr;

    float* spikes = out;
    float* mems   = out + (size_t)N_BATCH * T_STEPS;
    const size_t rowbase = (size_t)n0 * T_STEPS;
    const float* xg = x + rowbase;

    #pragma unroll
    for (int k = 0; k < 8; ++k) {
        int idx = tid + k * BN, row = idx >> 3, col = idx & 7;
        cp_async16((uint32_t)__cvta_generic_to_shared(&bufA[row * PAD + col * 4]),
                   xg + (size_t)row * T_STEPS + col * 4);
    }
    cp_commit(); cp_wait0(); __syncthreads();

    float* cur = bufA; float* nxt = bufB;
    #pragma unroll 1
    for (int c = 0; c < NCHUNK; ++c) {
        if (c + 1 < NCHUNK) {
            const float* xgc = xg + (c + 1) * BT;
            #pragma unroll
            for (int k = 0; k < 8; ++k) {
                int idx = tid + k * BN, row = idx >> 3, col = idx & 7;
                cp_async16((uint32_t)__cvta_generic_to_shared(&nxt[row * PAD + col * 4]),
                           xgc + (size_t)row * T_STEPS + col * 4);
            }
            cp_commit();
        }
        {
            float* xr = &cur[tid * PAD];
            float* sr = &sspk[tid * PAD];
            #pragma unroll
            for (int t4 = 0; t4 < 8; ++t4) {
                float4 xv = *(float4*)&xr[t4 * 4];
                float4 mv, sv;
                mv.x = mem; float mu = fmaf(beta, mem, xv.x);
                sv.x = (mu >= thr) ? 1.0f : 0.0f; mem = fmaf(-sv.x, thr, mu);
                mv.y = mem; mu = fmaf(beta, mem, xv.y);
                sv.y = (mu >= thr) ? 1.0f : 0.0f; mem = fmaf(-sv.y, thr, mu);
                mv.z = mem; mu = fmaf(beta, mem, xv.z);
                sv.z = (mu >= thr) ? 1.0f : 0.0f; mem = fmaf(-sv.z, thr, mu);
                mv.w = mem; mu = fmaf(beta, mem, xv.w);
                sv.w = (mu >= thr) ? 1.0f : 0.0f; mem = fmaf(-sv.w, thr, mu);
                *(float4*)&xr[t4 * 4] = mv;
                *(float4*)&sr[t4 * 4] = sv;
            }
        }
        __syncthreads();
        {
            float4* sg4 = (float4*)(spikes + rowbase + c * BT);
            float4* mg4 = (float4*)(mems   + rowbase + c * BT);
            #pragma unroll
            for (int k = 0; k < 8; ++k) {
                int idx = tid + k * BN, row = idx >> 3, col = idx & 7;
                mg4[(size_t)row * (T_STEPS / 4) + col] = *(const float4*)&cur[row * PAD + col * 4];
                sg4[(size_t)row * (T_STEPS / 4) + col] = *(const float4*)&sspk[row * PAD + col * 4];
            }
        }
        cp_wait0(); __syncthreads();
        float* tmp = cur; cur = nxt; nxt = tmp;
    }
}

// ---------------- host ----------------
typedef CUresult (*EncodeFn)(CUtensorMap*, CUtensorMapDataType, cuuint32_t, void*,
                             const cuuint64_t*, const cuuint64_t*, const cuuint32_t*,
                             const cuuint32_t*, CUtensorMapInterleave, CUtensorMapSwizzle,
                             CUtensorMapL2promotion, CUtensorMapFloatOOBfill);

extern "C" void kernel_launch(void* const* d_in, const int* in_sizes, int n_in,
                              void* d_out, int out_size)
{
    const float* x      = (const float*)d_in[0];
    const float* beta_  = (const float*)d_in[1];
    const float* thresh = (const float*)d_in[2];
    const float* init_u = (const float*)d_in[3];
    float* out = (float*)d_out;

    void* sym = nullptr;
    cudaDriverEntryPointQueryResult qr;
    cudaGetDriverEntryPointByVersion("cuTensorMapEncodeTiled", &sym, 12000,
                                     cudaEnableDefault, &qr);

    bool tma_ok = false;
    CUtensorMap x_map, mem_map;
    if (sym) {
        EncodeFn enc = (EncodeFn)sym;
        cuuint64_t dims[2]    = {T_STEPS, N_BATCH};
        cuuint64_t strides[1] = {T_STEPS * sizeof(float)};
        cuuint32_t box[2]     = {BT, 32};        // 128B x 32 rows per warp tile
        cuuint32_t estr[2]    = {1, 1};
        CUresult r1 = enc(&x_map, CU_TENSOR_MAP_DATA_TYPE_FLOAT32, 2, (void*)x,
                          dims, strides, box, estr,
                          CU_TENSOR_MAP_INTERLEAVE_NONE, CU_TENSOR_MAP_SWIZZLE_128B,
                          CU_TENSOR_MAP_L2_PROMOTION_L2_128B, CU_TENSOR_MAP_FLOAT_OOB_FILL_NONE);
        void* mems_base = (void*)(out + (size_t)N_BATCH * T_STEPS);
        CUresult r2 = enc(&mem_map, CU_TENSOR_MAP_DATA_TYPE_FLOAT32, 2, mems_base,
                          dims, strides, box, estr,
                          CU_TENSOR_MAP_INTERLEAVE_NONE, CU_TENSOR_MAP_SWIZZLE_128B,
                          CU_TENSOR_MAP_L2_PROMOTION_L2_128B, CU_TENSOR_MAP_FLOAT_OOB_FILL_NONE);
        tma_ok = (r1 == CUDA_SUCCESS) && (r2 == CUDA_SUCCESS);
    }

    if (tma_ok) {
        cudaFuncSetAttribute(lif_tma_kernel,
                             cudaFuncAttributeMaxDynamicSharedMemorySize, SMEM_TOTAL);
        lif_tma_kernel<<<N_BATCH / BN, BN, SMEM_TOTAL>>>(
            x_map, mem_map, beta_, thresh, init_u, out);
    } else {
        cudaFuncSetAttribute(lif_fallback,
                             cudaFuncAttributeMaxDynamicSharedMemorySize, FB_SMEM);
        lif_fallback<<<N_BATCH / BN, BN, FB_SMEM>>>(x, beta_, thresh, init_u, out);
    }
}

// round 7
// speedup vs baseline: 1.0437x; 1.0437x over previous
#include <cuda_runtime.h>
#include <cuda.h>
#include <cstdint>

#define N_BATCH 65536
#define T_STEPS 512
#define BN 64                      // threads per block (2 warps) -> fine-grained load balance
#define BT 32                      // timesteps per chunk (128B rows -> SW128)
#define NCHUNK (T_STEPS / BT)      // 16
#define WTILE_BYTES (32 * BT * 4)  // 4096: one warp's 32 rows x 128B
#define NBUF 3
#define NWARPS (BN / 32)
#define SMEM_TOTAL (1024 + NWARPS * NBUF * WTILE_BYTES)   // 1024 + 24KB -> 8 CTAs/SM

// ---------------- PTX helpers ----------------
__device__ __forceinline__ uint32_t smem_u32(const void* p) {
    return (uint32_t)__cvta_generic_to_shared(p);
}
__device__ __forceinline__ void mbar_init(uint32_t mbar, uint32_t cnt) {
    asm volatile("mbarrier.init.shared.b64 [%0], %1;" :: "r"(mbar), "r"(cnt) : "memory");
}
__device__ __forceinline__ void mbar_expect_tx(uint32_t mbar, uint32_t bytes) {
    asm volatile("mbarrier.arrive.expect_tx.shared.b64 _, [%0], %1;"
                 :: "r"(mbar), "r"(bytes) : "memory");
}
__device__ __forceinline__ void mbar_wait(uint32_t mbar, uint32_t parity) {
    asm volatile(
        "{\n\t.reg .pred P;\n"
        "WAITLOOP_%=:\n\t"
        "mbarrier.try_wait.parity.acquire.cta.shared::cta.b64 P, [%0], %1, 0x989680;\n\t"
        "@P bra.uni WAITDONE_%=;\n\t"
        "bra.uni WAITLOOP_%=;\n"
        "WAITDONE_%=:\n\t}"
        :: "r"(mbar), "r"(parity) : "memory");
}
__device__ __forceinline__ void tma_load2d(uint32_t smem_dst, const CUtensorMap* map,
                                           int cx, int cy, uint32_t mbar) {
    asm volatile("cp.async.bulk.tensor.2d.shared::cta.global.tile.mbarrier::complete_tx::bytes"
                 " [%0], [%1, {%2, %3}], [%4];"
                 :: "r"(smem_dst), "l"(map), "r"(cx), "r"(cy), "r"(mbar) : "memory");
}
__device__ __forceinline__ void tma_store2d(const CUtensorMap* map, int cx, int cy,
                                            uint32_t smem_src) {
    asm volatile("cp.async.bulk.tensor.2d.global.shared::cta.tile.bulk_group"
                 " [%0, {%1, %2}], [%3];"
                 :: "l"(map), "r"(cx), "r"(cy), "r"(smem_src) : "memory");
}
__device__ __forceinline__ void tma_commit() {
    asm volatile("cp.async.bulk.commit_group;" ::: "memory");
}
__device__ __forceinline__ void tma_wait_read1() {
    asm volatile("cp.async.bulk.wait_group.read 1;" ::: "memory");
}
__device__ __forceinline__ void tma_wait_all() {
    asm volatile("cp.async.bulk.wait_group 0;" ::: "memory");
}
__device__ __forceinline__ void fence_proxy_async_cta() {
    asm volatile("fence.proxy.async.shared::cta;" ::: "memory");
}

// SW128 swizzle for 128B rows: 16B unit u at row r lives at r*128 + (u ^ (r&7))*16
__device__ __forceinline__ uint32_t sw_off(int row, int u) {
    return (uint32_t)(row * 128 + ((u ^ (row & 7)) << 4));
}

// ---------------- warp-autonomous TMA kernel ----------------
__global__ __launch_bounds__(BN) void lif_tma_kernel(
    const __grid_constant__ CUtensorMap x_map,
    const __grid_constant__ CUtensorMap mem_map,
    const float* __restrict__ beta_p,
    const float* __restrict__ thr_p,
    const float* __restrict__ init_u,
    float* __restrict__ out)
{
    extern __shared__ char smem[];
    uint32_t mbar_base = smem_u32(smem);        // NWARPS*NBUF mbarriers, 8B each
    char* tiles = smem + 1024;                  // 1024-aligned tiles

    const int tid  = threadIdx.x;
    const int lane = tid & 31;
    const int w    = tid >> 5;
    const int n0   = blockIdx.x * BN;
    const int nw0  = n0 + w * 32;               // this warp's first neuron row

    const float beta = 1.0f / (1.0f + __expf(-beta_p[0]));
    const float thr  = thr_p[0];
    float mem = init_u[nw0 + lane] * thr;

    float* spikes = out;

    char* wtiles = tiles + w * NBUF * WTILE_BYTES;
    const uint32_t wmbar = mbar_base + (uint32_t)(w * NBUF) * 8u;

    if (tid < NWARPS * NBUF) mbar_init(mbar_base + tid * 8u, 1);
    __syncthreads();

    if (lane == 0) {
        fence_proxy_async_cta();
        mbar_expect_tx(wmbar + 0, WTILE_BYTES);
        tma_load2d(smem_u32(wtiles + 0 * WTILE_BYTES), &x_map, 0, nw0, wmbar + 0);
        mbar_expect_tx(wmbar + 8, WTILE_BYTES);
        tma_load2d(smem_u32(wtiles + 1 * WTILE_BYTES), &x_map, BT, nw0, wmbar + 8);
    }

    const int g8  = lane & 7;                   // ballot group this lane keeps
    const int sub = lane >> 3;                  // 0..3

    #pragma unroll 1
    for (int c = 0; c < NCHUNK; ++c) {
        const int buf = c % NBUF;
        char* tile = wtiles + buf * WTILE_BYTES;

        mbar_wait(wmbar + 8u * buf, (uint32_t)((c / NBUF) & 1));

        // ---- scan: read x (SW128), write mem_in in place, collect ballots ----
        uint32_t k0 = 0, k1 = 0, k2 = 0, k3 = 0;
        #pragma unroll
        for (int t4 = 0; t4 < 8; ++t4) {
            float4* slot = (float4*)(tile + sw_off(lane, t4));
            float4 xv = *slot;
            float4 mv;
            uint32_t b0, b1, b2, b3;

            mv.x = mem;
            float mu = fmaf(beta, mem, xv.x);
            float s  = mu - thr;
            bool  p  = (s >= 0.0f);
            b0 = __ballot_sync(0xffffffffu, p);
            mem = p ? s : mu;

            mv.y = mem;
            mu = fmaf(beta, mem, xv.y);
            s  = mu - thr;
            p  = (s >= 0.0f);
            b1 = __ballot_sync(0xffffffffu, p);
            mem = p ? s : mu;

            mv.z = mem;
            mu = fmaf(beta, mem, xv.z);
            s  = mu - thr;
            p  = (s >= 0.0f);
            b2 = __ballot_sync(0xffffffffu, p);
            mem = p ? s : mu;

            mv.w = mem;
            mu = fmaf(beta, mem, xv.w);
            s  = mu - thr;
            p  = (s >= 0.0f);
            b3 = __ballot_sync(0xffffffffu, p);
            mem = p ? s : mu;

            *slot = mv;                          // mem_in tile, in place (SW128)

            if (g8 == t4) { k0 = b0; k1 = b1; k2 = b2; k3 = b3; }
        }
        __syncwarp();                            // warp's 32 rows all written

        // ---- lane 0: TMA store mem tile; prefetch chunk c+2 (warp-local) ----
        if (lane == 0) {
            fence_proxy_async_cta();
            tma_store2d(&mem_map, c * BT, nw0, smem_u32(tile));
            tma_commit();
            if (c + 2 < NCHUNK) {
                tma_wait_read1();                // store c-1 read-done -> buffer free
                const int nbuf = (c + 2) % NBUF;
                mbar_expect_tx(wmbar + 8u * nbuf, WTILE_BYTES);
                tma_load2d(smem_u32(wtiles + nbuf * WTILE_BYTES), &x_map,
                           (c + 2) * BT, nw0, wmbar + 8u * nbuf);
            }
        }

        // ---- spikes: bit-extract from ballots, coalesced STG.128 ----
        {
            const int tbase = c * BT + g8 * 4;
            #pragma unroll
            for (int pp = 0; pp < 8; ++pp) {
                const int bit = pp * 4 + sub;
                const int n   = nw0 + pp * 4 + sub;
                float4 sv;
                sv.x = ((k0 >> bit) & 1u) ? 1.0f : 0.0f;
                sv.y = ((k1 >> bit) & 1u) ? 1.0f : 0.0f;
                sv.z = ((k2 >> bit) & 1u) ? 1.0f : 0.0f;
                sv.w = ((k3 >> bit) & 1u) ? 1.0f : 0.0f;
                *(float4*)(spikes + (size_t)n * T_STEPS + tbase) = sv;
            }
        }
    }

    if (lane == 0) tma_wait_all();               // drain this warp's mem stores
}

// ---------------- fallback (Round-3 kernel, proven) ----------------
#define FBN 128
#define PAD 36
#define TILE_W (FBN * PAD)
#define FB_SMEM (3 * TILE_W * 4)

__device__ __forceinline__ void cp_async16(uint32_t smem_addr, const void* gptr) {
    asm volatile("cp.async.cg.shared.global [%0], [%1], 16;\n"
                 :: "r"(smem_addr), "l"(gptr) : "memory");
}
__device__ __forceinline__ void cp_commit() {
    asm volatile("cp.async.commit_group;\n" ::: "memory");
}
__device__ __forceinline__ void cp_wait0() {
    asm volatile("cp.async.wait_group 0;\n" ::: "memory");
}

__global__ __launch_bounds__(FBN) void lif_fallback(
    const float* __restrict__ x, const float* __restrict__ beta_p,
    const float* __restrict__ thr_p, const float* __restrict__ init_u,
    float* __restrict__ out)
{
    extern __shared__ float smemf[];
    float* bufA = smemf;
    float* bufB = smemf + TILE_W;
    float* sspk = smemf + 2 * TILE_W;

    const int tid = threadIdx.x;
    const int n0  = blockIdx.x * FBN;
    const float beta = 1.0f / (1.0f + __expf(-beta_p[0]));
    const float thr  = thr_p[0];
    float mem = init_u[n0 + tid] * thr;

    float* spikes = out;
    float* mems   = out + (size_t)N_BATCH * T_STEPS;
    const size_t rowbase = (size_t)n0 * T_STEPS;
    const float* xg = x + rowbase;

    #pragma unroll
    for (int k = 0; k < 8; ++k) {
        int idx = tid + k * FBN, row = idx >> 3, col = idx & 7;
        cp_async16((uint32_t)__cvta_generic_to_shared(&bufA[row * PAD + col * 4]),
                   xg + (size_t)row * T_STEPS + col * 4);
    }
    cp_commit(); cp_wait0(); __syncthreads();

    float* cur = bufA; float* nxt = bufB;
    #pragma unroll 1
    for (int c = 0; c < NCHUNK; ++c) {
        if (c + 1 < NCHUNK) {
            const float* xgc = xg + (c + 1) * BT;
            #pragma unroll
            for (int k = 0; k < 8; ++k) {
                int idx = tid + k * FBN, row = idx >> 3, col = idx & 7;
                cp_async16((uint32_t)__cvta_generic_to_shared(&nxt[row * PAD + col * 4]),
                           xgc + (size_t)row * T_STEPS + col * 4);
            }
            cp_commit();
        }
        {
            float* xr = &cur[tid * PAD];
            float* sr = &sspk[tid * PAD];
            #pragma unroll
            for (int t4 = 0; t4 < 8; ++t4) {
                float4 xv = *(float4*)&xr[t4 * 4];
                float4 mv, sv;
                mv.x = mem; float mu = fmaf(beta, mem, xv.x);
                sv.x = (mu >= thr) ? 1.0f : 0.0f; mem = fmaf(-sv.x, thr, mu);
                mv.y = mem; mu = fmaf(beta, mem, xv.y);
                sv.y = (mu >= thr) ? 1.0f : 0.0f; mem = fmaf(-sv.y, thr, mu);
                mv.z = mem; mu = fmaf(beta, mem, xv.z);
                sv.z = (mu >= thr) ? 1.0f : 0.0f; mem = fmaf(-sv.z, thr, mu);
                mv.w = mem; mu = fmaf(beta, mem, xv.w);
                sv.w = (mu >= thr) ? 1.0f : 0.0f; mem = fmaf(-sv.w, thr, mu);
                *(float4*)&xr[t4 * 4] = mv;
                *(float4*)&sr[t4 * 4] = sv;
            }
        }
        __syncthreads();
        {
            float4* sg4 = (float4*)(spikes + rowbase + c * BT);
            float4* mg4 = (float4*)(mems   + rowbase + c * BT);
            #pragma unroll
            for (int k = 0; k < 8; ++k) {
                int idx = tid + k * FBN, row = idx >> 3, col = idx & 7;
                mg4[(size_t)row * (T_STEPS / 4) + col] = *(const float4*)&cur[row * PAD + col * 4];
                sg4[(size_t)row * (T_STEPS / 4) + col] = *(const float4*)&sspk[row * PAD + col * 4];
            }
        }
        cp_wait0(); __syncthreads();
        float* tmp = cur; cur = nxt; nxt = tmp;
    }
}

// ---------------- host ----------------
typedef CUresult (*EncodeFn)(CUtensorMap*, CUtensorMapDataType, cuuint32_t, void*,
                             const cuuint64_t*, const cuuint64_t*, const cuuint32_t*,
                             const cuuint32_t*, CUtensorMapInterleave, CUtensorMapSwizzle,
                             CUtensorMapL2promotion, CUtensorMapFloatOOBfill);

extern "C" void kernel_launch(void* const* d_in, const int* in_sizes, int n_in,
                              void* d_out, int out_size)
{
    const float* x      = (const float*)d_in[0];
    const float* beta_  = (const float*)d_in[1];
    const float* thresh = (const float*)d_in[2];
    const float* init_u = (const float*)d_in[3];
    float* out = (float*)d_out;

    void* sym = nullptr;
    cudaDriverEntryPointQueryResult qr;
    cudaGetDriverEntryPointByVersion("cuTensorMapEncodeTiled", &sym, 12000,
                                     cudaEnableDefault, &qr);

    bool tma_ok = false;
    CUtensorMap x_map, mem_map;
    if (sym) {
        EncodeFn enc = (EncodeFn)sym;
        cuuint64_t dims[2]    = {T_STEPS, N_BATCH};
        cuuint64_t strides[1] = {T_STEPS * sizeof(float)};
        cuuint32_t box[2]     = {BT, 32};        // 128B x 32 rows per warp tile
        cuuint32_t estr[2]    = {1, 1};
        CUresult r1 = enc(&x_map, CU_TENSOR_MAP_DATA_TYPE_FLOAT32, 2, (void*)x,
                          dims, strides, box, estr,
                          CU_TENSOR_MAP_INTERLEAVE_NONE, CU_TENSOR_MAP_SWIZZLE_128B,
                          CU_TENSOR_MAP_L2_PROMOTION_L2_128B, CU_TENSOR_MAP_FLOAT_OOB_FILL_NONE);
        void* mems_base = (void*)(out + (size_t)N_BATCH * T_STEPS);
        CUresult r2 = enc(&mem_map, CU_TENSOR_MAP_DATA_TYPE_FLOAT32, 2, mems_base,
                          dims, strides, box, estr,
                          CU_TENSOR_MAP_INTERLEAVE_NONE, CU_TENSOR_MAP_SWIZZLE_128B,
                          CU_TENSOR_MAP_L2_PROMOTION_L2_128B, CU_TENSOR_MAP_FLOAT_OOB_FILL_NONE);
        tma_ok = (r1 == CUDA_SUCCESS) && (r2 == CUDA_SUCCESS);
    }

    if (tma_ok) {
        cudaFuncSetAttribute(lif_tma_kernel,
                             cudaFuncAttributeMaxDynamicSharedMemorySize, SMEM_TOTAL);
        lif_tma_kernel<<<N_BATCH / BN, BN, SMEM_TOTAL>>>(
            x_map, mem_map, beta_, thresh, init_u, out);
    } else {
        cudaFuncSetAttribute(lif_fallback,
                             cudaFuncAttributeMaxDynamicSharedMemorySize, FB_SMEM);
        lif_fallback<<<N_BATCH / FBN, FBN, FB_SMEM>>>(x, beta_, thresh, init_u, out);
    }
}

// round 9
// speedup vs baseline: 1.0749x; 1.0299x over previous
#include <cuda_runtime.h>
#include <cuda.h>
#include <cstdint>

#define N_BATCH 65536
#define T_STEPS 512
#define BN 64                      // threads per block (2 warps)
#define BT 32                      // timesteps per chunk (128B rows -> SW128)
#define NCHUNK (T_STEPS / BT)      // 16
#define WTILE_BYTES (32 * BT * 4)  // 4096: one warp's 32 rows x 128B
#define NBUF 3
#define NWARPS (BN / 32)
#define SMEM_TOTAL (1024 + NWARPS * NBUF * WTILE_BYTES)   // 25.6KB -> 8 CTAs/SM

// ---------------- PTX helpers ----------------
__device__ __forceinline__ uint32_t smem_u32(const void* p) {
    return (uint32_t)__cvta_generic_to_shared(p);
}
__device__ __forceinline__ void mbar_init(uint32_t mbar, uint32_t cnt) {
    asm volatile("mbarrier.init.shared.b64 [%0], %1;" :: "r"(mbar), "r"(cnt) : "memory");
}
__device__ __forceinline__ void mbar_expect_tx(uint32_t mbar, uint32_t bytes) {
    asm volatile("mbarrier.arrive.expect_tx.shared.b64 _, [%0], %1;"
                 :: "r"(mbar), "r"(bytes) : "memory");
}
__device__ __forceinline__ void mbar_wait(uint32_t mbar, uint32_t parity) {
    asm volatile(
        "{\n\t.reg .pred P;\n"
        "WAITLOOP_%=:\n\t"
        "mbarrier.try_wait.parity.acquire.cta.shared::cta.b64 P, [%0], %1, 0x989680;\n\t"
        "@P bra.uni WAITDONE_%=;\n\t"
        "bra.uni WAITLOOP_%=;\n"
        "WAITDONE_%=:\n\t}"
        :: "r"(mbar), "r"(parity) : "memory");
}
__device__ __forceinline__ void tma_load2d(uint32_t smem_dst, const CUtensorMap* map,
                                           int cx, int cy, uint32_t mbar) {
    asm volatile("cp.async.bulk.tensor.2d.shared::cta.global.tile.mbarrier::complete_tx::bytes"
                 " [%0], [%1, {%2, %3}], [%4];"
                 :: "r"(smem_dst), "l"(map), "r"(cx), "r"(cy), "r"(mbar) : "memory");
}
__device__ __forceinline__ void tma_store2d(const CUtensorMap* map, int cx, int cy,
                                            uint32_t smem_src) {
    asm volatile("cp.async.bulk.tensor.2d.global.shared::cta.tile.bulk_group"
                 " [%0, {%1, %2}], [%3];"
                 :: "l"(map), "r"(cx), "r"(cy), "r"(smem_src) : "memory");
}
__device__ __forceinline__ void tma_commit() {
    asm volatile("cp.async.bulk.commit_group;" ::: "memory");
}
__device__ __forceinline__ void tma_wait_read0() {
    asm volatile("cp.async.bulk.wait_group.read 0;" ::: "memory");
}
__device__ __forceinline__ void tma_wait_all() {
    asm volatile("cp.async.bulk.wait_group 0;" ::: "memory");
}
__device__ __forceinline__ void fence_proxy_async_cta() {
    asm volatile("fence.proxy.async.shared::cta;" ::: "memory");
}

// SW128 swizzle for 128B rows: 16B unit u at row r lives at r*128 + (u ^ (r&7))*16
__device__ __forceinline__ uint32_t sw_off(int row, int u) {
    return (uint32_t)(row * 128 + ((u ^ (row & 7)) << 4));
}

// ---------------- warp-autonomous TMA kernel, 3-deep prefetch ----------------
__global__ __launch_bounds__(BN) void lif_tma_kernel(
    const __grid_constant__ CUtensorMap x_map,
    const __grid_constant__ CUtensorMap mem_map,
    const float* __restrict__ beta_p,
    const float* __restrict__ thr_p,
    const float* __restrict__ init_u,
    float* __restrict__ out)
{
    extern __shared__ char smem[];
    uint32_t mbar_base = smem_u32(smem);        // NWARPS*NBUF mbarriers, 8B each
    char* tiles = smem + 1024;

    const int tid  = threadIdx.x;
    const int lane = tid & 31;
    const int w    = tid >> 5;
    const int n0   = blockIdx.x * BN;
    const int nw0  = n0 + w * 32;               // this warp's first neuron row

    const float beta = 1.0f / (1.0f + __expf(-beta_p[0]));
    const float thr  = thr_p[0];
    float mem = init_u[nw0 + lane] * thr;

    float* spikes = out;

    char* wtiles = tiles + w * NBUF * WTILE_BYTES;
    const uint32_t wmbar = mbar_base + (uint32_t)(w * NBUF) * 8u;

    if (tid < NWARPS * NBUF) mbar_init(mbar_base + tid * 8u, 1);
    __syncthreads();

    // prologue: fill ALL 3 buffers (chunks 0,1,2)
    if (lane == 0) {
        fence_proxy_async_cta();
        #pragma unroll
        for (int b = 0; b < NBUF; ++b) {
            mbar_expect_tx(wmbar + 8u * b, WTILE_BYTES);
            tma_load2d(smem_u32(wtiles + b * WTILE_BYTES), &x_map, b * BT, nw0,
                       wmbar + 8u * b);
        }
    }

    const int g8  = lane & 7;                   // ballot group this lane keeps
    const int sub = lane >> 3;                  // 0..3

    #pragma unroll 1
    for (int c = 0; c < NCHUNK; ++c) {
        const int buf = c % NBUF;
        char* tile = wtiles + buf * WTILE_BYTES;

        mbar_wait(wmbar + 8u * buf, (uint32_t)((c / NBUF) & 1));

        // ---- scan: read x (SW128), write mem_in in place, collect ballots ----
        uint32_t k0 = 0, k1 = 0, k2 = 0, k3 = 0;
        #pragma unroll
        for (int t4 = 0; t4 < 8; ++t4) {
            float4* slot = (float4*)(tile + sw_off(lane, t4));
            float4 xv = *slot;
            float4 mv;
            uint32_t b0, b1, b2, b3;

            mv.x = mem;
            float mu = fmaf(beta, mem, xv.x);
            float s  = mu - thr;
            bool  p  = (s >= 0.0f);
            b0 = __ballot_sync(0xffffffffu, p);
            mem = p ? s : mu;

            mv.y = mem;
            mu = fmaf(beta, mem, xv.y);
            s  = mu - thr;
            p  = (s >= 0.0f);
            b1 = __ballot_sync(0xffffffffu, p);
            mem = p ? s : mu;

            mv.z = mem;
            mu = fmaf(beta, mem, xv.z);
            s  = mu - thr;
            p  = (s >= 0.0f);
            b2 = __ballot_sync(0xffffffffu, p);
            mem = p ? s : mu;

            mv.w = mem;
            mu = fmaf(beta, mem, xv.w);
            s  = mu - thr;
            p  = (s >= 0.0f);
            b3 = __ballot_sync(0xffffffffu, p);
            mem = p ? s : mu;

            *slot = mv;                          // mem_in tile, in place (SW128)

            if (g8 == t4) { k0 = b0; k1 = b1; k2 = b2; k3 = b3; }
        }
        __syncwarp();                            // warp's 32 rows all written

        // ---- lane 0: store mem tile, then immediately refill this buffer ----
        if (lane == 0) {
            fence_proxy_async_cta();
            tma_store2d(&mem_map, c * BT, nw0, smem_u32(tile));
            tma_commit();
            if (c + NBUF < NCHUNK) {
                tma_wait_read0();                // drain store c's smem read (fast)
                mbar_expect_tx(wmbar + 8u * buf, WTILE_BYTES);
                tma_load2d(smem_u32(tile), &x_map, (c + NBUF) * BT, nw0,
                           wmbar + 8u * buf);
            }
        }

        // ---- spikes: bit-extract from ballots, coalesced STG.128 ----
        {
            const int tbase = c * BT + g8 * 4;
            #pragma unroll
            for (int pp = 0; pp < 8; ++pp) {
                const int bit = pp * 4 + sub;
                const int n   = nw0 + pp * 4 + sub;
                float4 sv;
                sv.x = ((k0 >> bit) & 1u) ? 1.0f : 0.0f;
                sv.y = ((k1 >> bit) & 1u) ? 1.0f : 0.0f;
                sv.z = ((k2 >> bit) & 1u) ? 1.0f : 0.0f;
                sv.w = ((k3 >> bit) & 1u) ? 1.0f : 0.0f;
                *(float4*)(spikes + (size_t)n * T_STEPS + tbase) = sv;
            }
        }
    }

    if (lane == 0) tma_wait_all();               // drain this warp's mem stores
}

// ---------------- fallback (Round-3 kernel, proven) ----------------
#define FBN 128
#define PAD 36
#define TILE_W (FBN * PAD)
#define FB_SMEM (3 * TILE_W * 4)

__device__ __forceinline__ void cp_async16(uint32_t smem_addr, const void* gptr) {
    asm volatile("cp.async.cg.shared.global [%0], [%1], 16;\n"
                 :: "r"(smem_addr), "l"(gptr) : "memory");
}
__device__ __forceinline__ void cp_commit() {
    asm volatile("cp.async.commit_group;\n" ::: "memory");
}
__device__ __forceinline__ void cp_wait0() {
    asm volatile("cp.async.wait_group 0;\n" ::: "memory");
}

__global__ __launch_bounds__(FBN) void lif_fallback(
    const float* __restrict__ x, const float* __restrict__ beta_p,
    const float* __restrict__ thr_p, const float* __restrict__ init_u,
    float* __restrict__ out)
{
    extern __shared__ float smemf[];
    float* bufA = smemf;
    float* bufB = smemf + TILE_W;
    float* sspk = smemf + 2 * TILE_W;

    const int tid = threadIdx.x;
    const int n0  = blockIdx.x * FBN;
    const float beta = 1.0f / (1.0f + __expf(-beta_p[0]));
    const float thr  = thr_p[0];
    float mem = init_u[n0 + tid] * thr;

    float* spikes = out;
    float* mems   = out + (size_t)N_BATCH * T_STEPS;
    const size_t rowbase = (size_t)n0 * T_STEPS;
    const float* xg = x + rowbase;

    #pragma unroll
    for (int k = 0; k < 8; ++k) {
        int idx = tid + k * FBN, row = idx >> 3, col = idx & 7;
        cp_async16((uint32_t)__cvta_generic_to_shared(&bufA[row * PAD + col * 4]),
                   xg + (size_t)row * T_STEPS + col * 4);
    }
    cp_commit(); cp_wait0(); __syncthreads();

    float* cur = bufA; float* nxt = bufB;
    #pragma unroll 1
    for (int c = 0; c < NCHUNK; ++c) {
        if (c + 1 < NCHUNK) {
            const float* xgc = xg + (c + 1) * BT;
            #pragma unroll
            for (int k = 0; k < 8; ++k) {
                int idx = tid + k * FBN, row = idx >> 3, col = idx & 7;
                cp_async16((uint32_t)__cvta_generic_to_shared(&nxt[row * PAD + col * 4]),
                           xgc + (size_t)row * T_STEPS + col * 4);
            }
            cp_commit();
        }
        {
            float* xr = &cur[tid * PAD];
            float* sr = &sspk[tid * PAD];
            #pragma unroll
            for (int t4 = 0; t4 < 8; ++t4) {
                float4 xv = *(float4*)&xr[t4 * 4];
                float4 mv, sv;
                mv.x = mem; float mu = fmaf(beta, mem, xv.x);
                sv.x = (mu >= thr) ? 1.0f : 0.0f; mem = fmaf(-sv.x, thr, mu);
                mv.y = mem; mu = fmaf(beta, mem, xv.y);
                sv.y = (mu >= thr) ? 1.0f : 0.0f; mem = fmaf(-sv.y, thr, mu);
                mv.z = mem; mu = fmaf(beta, mem, xv.z);
                sv.z = (mu >= thr) ? 1.0f : 0.0f; mem = fmaf(-sv.z, thr, mu);
                mv.w = mem; mu = fmaf(beta, mem, xv.w);
                sv.w = (mu >= thr) ? 1.0f : 0.0f; mem = fmaf(-sv.w, thr, mu);
                *(float4*)&xr[t4 * 4] = mv;
                *(float4*)&sr[t4 * 4] = sv;
            }
        }
        __syncthreads();
        {
            float4* sg4 = (float4*)(spikes + rowbase + c * BT);
            float4* mg4 = (float4*)(mems   + rowbase + c * BT);
            #pragma unroll
            for (int k = 0; k < 8; ++k) {
                int idx = tid + k * FBN, row = idx >> 3, col = idx & 7;
                mg4[(size_t)row * (T_STEPS / 4) + col] = *(const float4*)&cur[row * PAD + col * 4];
                sg4[(size_t)row * (T_STEPS / 4) + col] = *(const float4*)&sspk[row * PAD + col * 4];
            }
        }
        cp_wait0(); __syncthreads();
        float* tmp = cur; cur = nxt; nxt = tmp;
    }
}

// ---------------- host ----------------
typedef CUresult (*EncodeFn)(CUtensorMap*, CUtensorMapDataType, cuuint32_t, void*,
                             const cuuint64_t*, const cuuint64_t*, const cuuint32_t*,
                             const cuuint32_t*, CUtensorMapInterleave, CUtensorMapSwizzle,
                             CUtensorMapL2promotion, CUtensorMapFloatOOBfill);

extern "C" void kernel_launch(void* const* d_in, const int* in_sizes, int n_in,
                              void* d_out, int out_size)
{
    const float* x      = (const float*)d_in[0];
    const float* beta_  = (const float*)d_in[1];
    const float* thresh = (const float*)d_in[2];
    const float* init_u = (const float*)d_in[3];
    float* out = (float*)d_out;

    void* sym = nullptr;
    cudaDriverEntryPointQueryResult qr;
    cudaGetDriverEntryPointByVersion("cuTensorMapEncodeTiled", &sym, 12000,
                                     cudaEnableDefault, &qr);

    bool tma_ok = false;
    CUtensorMap x_map, mem_map;
    if (sym) {
        EncodeFn enc = (EncodeFn)sym;
        cuuint64_t dims[2]    = {T_STEPS, N_BATCH};
        cuuint64_t strides[1] = {T_STEPS * sizeof(float)};
        cuuint32_t box[2]     = {BT, 32};        // 128B x 32 rows per warp tile
        cuuint32_t estr[2]    = {1, 1};
        CUresult r1 = enc(&x_map, CU_TENSOR_MAP_DATA_TYPE_FLOAT32, 2, (void*)x,
                          dims, strides, box, estr,
                          CU_TENSOR_MAP_INTERLEAVE_NONE, CU_TENSOR_MAP_SWIZZLE_128B,
                          CU_TENSOR_MAP_L2_PROMOTION_L2_128B, CU_TENSOR_MAP_FLOAT_OOB_FILL_NONE);
        void* mems_base = (void*)(out + (size_t)N_BATCH * T_STEPS);
        CUresult r2 = enc(&mem_map, CU_TENSOR_MAP_DATA_TYPE_FLOAT32, 2, mems_base,
                          dims, strides, box, estr,
                          CU_TENSOR_MAP_INTERLEAVE_NONE, CU_TENSOR_MAP_SWIZZLE_128B,
                          CU_TENSOR_MAP_L2_PROMOTION_L2_128B, CU_TENSOR_MAP_FLOAT_OOB_FILL_NONE);
        tma_ok = (r1 == CUDA_SUCCESS) && (r2 == CUDA_SUCCESS);
    }

    if (tma_ok) {
        cudaFuncSetAttribute(lif_tma_kernel,
                             cudaFuncAttributeMaxDynamicSharedMemorySize, SMEM_TOTAL);
        lif_tma_kernel<<<N_BATCH / BN, BN, SMEM_TOTAL>>>(
            x_map, mem_map, beta_, thresh, init_u, out);
    } else {
        cudaFuncSetAttribute(lif_fallback,
                             cudaFuncAttributeMaxDynamicSharedMemorySize, FB_SMEM);
        lif_fallback<<<N_BATCH / FBN, FBN, FB_SMEM>>>(x, beta_, thresh, init_u, out);
    }
}